// round 9
// baseline (speedup 1.0000x reference)
#include <cuda_runtime.h>
#include <cuda_bf16.h>
#include <math.h>
#include <float.h>
#include <stdint.h>

#define BSZ   256
#define MROW  32768
#define DIM   512
#define KNEG  10
#define MARGIN_F 0.1f
#define EPS_F 1e-6f
#define TMARGIN_F 0.31622776601683794f

#define BN 64               // j rows per CTA
#define BKC 32              // K per chunk (bf16)
#define NCHUNK (DIM / BKC)  // 16
#define NSTAGE 4
#define PADK 40             // padded k-stride in bf16 elems (80 B), ldsm conflict-free
#define STRB (PADK * 2)     // 80 bytes

// dynamic smem layout (bytes)
#define STAGE_SZ  25600                 // A 256*80 + B 64*80
#define A_OFF(s)  ((s) * STAGE_SZ)
#define B_OFF(s)  ((s) * STAGE_SZ + 20480)
#define NN_OFF    102400                // 64*8 u32 = 2048
#define TROW_OFF  104448                // 64 int
#define NNEG_OFF  76800                 // overlay of stage 3 (free until iter 0)
#define SMEM_DYN  104704
// epilogue tables overlay stage 0
#define T_TH  0
#define T_NA  1024
#define T_SA  2048
#define T_DAP 3072
#define T_NB  4096
#define T_SB  4352

#define CONV_BLOCKS (MROW / 8)          // 4096

// ---------------- scratch globals ----------------
__device__ float         g_thresh[BSZ];
__device__ float         g_na[BSZ];
__device__ float         g_sa[BSZ];
__device__ float         g_dap[BSZ];
__device__ int           g_nneg[BSZ * KNEG];
__device__ float         g_nb[MROW];
__device__ float         g_sb[MROW];
__device__ __align__(256) __nv_bfloat16 g_Abf[BSZ * DIM];
__device__ __align__(256) __nv_bfloat16 g_Bbf[(size_t)MROW * DIM];
__device__ double        g_total;
__device__ int           g_count;
__device__ unsigned      g_done = 0;

// ---------------- helpers ----------------
__device__ __forceinline__ uint32_t smem_u32(const void* p) {
    uint32_t a;
    asm("{ .reg .u64 t; cvta.to.shared.u64 t, %1; cvt.u32.u64 %0, t; }" : "=r"(a) : "l"(p));
    return a;
}
__device__ __forceinline__ void ldsm_x4(uint32_t* r, uint32_t addr) {
    asm volatile("ldmatrix.sync.aligned.m8n8.x4.shared.b16 {%0,%1,%2,%3}, [%4];"
                 : "=r"(r[0]), "=r"(r[1]), "=r"(r[2]), "=r"(r[3]) : "r"(addr));
}
__device__ __forceinline__ void mma16816(float* d, const uint32_t* a, uint32_t b0, uint32_t b1) {
    asm volatile(
        "mma.sync.aligned.m16n8k16.row.col.f32.bf16.bf16.f32 "
        "{%0,%1,%2,%3}, {%4,%5,%6,%7}, {%8,%9}, {%0,%1,%2,%3};"
        : "+f"(d[0]), "+f"(d[1]), "+f"(d[2]), "+f"(d[3])
        : "r"(a[0]), "r"(a[1]), "r"(a[2]), "r"(a[3]), "r"(b0), "r"(b1));
}
#define CP_ASYNC16(dst, src) \
    asm volatile("cp.async.cg.shared.global [%0], [%1], 16;" :: "r"(dst), "l"(src))
#define CP_COMMIT()   asm volatile("cp.async.commit_group;" ::: "memory")
#define CP_WAIT(n)    asm volatile("cp.async.wait_group %0;" :: "n"(n) : "memory")

__inline__ __device__ float warpReduceSum(float v) {
    #pragma unroll
    for (int o = 16; o > 0; o >>= 1) v += __shfl_down_sync(0xffffffffu, v, o);
    return v;
}
__inline__ __device__ int warpReduceSumI(int v) {
    #pragma unroll
    for (int o = 16; o > 0; o >>= 1) v += __shfl_down_sync(0xffffffffu, v, o);
    return v;
}
__device__ __forceinline__ uint32_t packbf(float x, float y) {
    __nv_bfloat162 t = __float22bfloat162_rn(make_float2(x, y));
    return *(uint32_t*)&t;
}

// ---------------- Kernel A: prep = B convert (+stats) AND per-query setup ----------------
__global__ __launch_bounds__(256)
void prep_kernel(const float* __restrict__ col,
                 const float* __restrict__ row,
                 const int* __restrict__ targets_col,
                 const int* __restrict__ qidxs,
                 const int* __restrict__ nnegs) {
    int bid = blockIdx.x;
    int tid = threadIdx.x;
    int w = tid >> 5, lid = tid & 31;

    if (bid < CONV_BLOCKS) {
        int j = bid * 8 + w;
        const float4* src = (const float4*)(row + (size_t)j * DIM);
        uint2* dst = (uint2*)(g_Bbf + (size_t)j * DIM);
        float nb = 0.f, sb = 0.f;
        #pragma unroll
        for (int t = 0; t < 4; t++) {
            float4 v = src[lid + t * 32];
            nb += v.x*v.x + v.y*v.y + v.z*v.z + v.w*v.w;
            sb += v.x + v.y + v.z + v.w;
            uint2 pk;
            pk.x = packbf(v.x, v.y);
            pk.y = packbf(v.z, v.w);
            dst[lid + t * 32] = pk;
        }
        nb = warpReduceSum(nb);
        sb = warpReduceSum(sb);
        if (lid == 0) { g_nb[j] = nb; g_sb[j] = sb; }
        return;
    }

    int i = bid - CONV_BLOCKS;
    const float* q = col + (size_t)i * DIM;
    const float* p = row + (size_t)(BSZ + i) * DIM;

    float na = 0.f, sa = 0.f, ps = 0.f, dap2 = 0.f;
    #pragma unroll
    for (int t = 0; t < 2; t++) {
        int k = tid + t * 256;
        float qv = q[k], pv = p[k];
        na += qv * qv;
        sa += qv;
        ps += qv * pv;
        float dlt = qv - pv + EPS_F;
        dap2 += dlt * dlt;
        g_Abf[i * DIM + k] = __float2bfloat16_rn(qv);
    }
    __shared__ float sh[4][8];
    na = warpReduceSum(na); sa = warpReduceSum(sa);
    ps = warpReduceSum(ps); dap2 = warpReduceSum(dap2);
    if (lid == 0) { sh[0][w] = na; sh[1][w] = sa; sh[2][w] = ps; sh[3][w] = dap2; }
    __syncthreads();

    if (w == 0) {
        int tc = targets_col[i];
        int qloc = 0, has = 0;
        #pragma unroll
        for (int g = 0; g < 8; g++) {
            int qv = qidxs[g * 32 + lid];
            unsigned word = __ballot_sync(0xffffffffu, qv == tc);
            if (!has && word) { qloc = g * 32 + __ffs(word) - 1; has = 1; }
        }
        if (lid < KNEG) g_nneg[i * KNEG + lid] = nnegs[qloc * KNEG + lid];
        if (lid == 0) {
            float rna = 0.f, rsa = 0.f, rps = 0.f, rdap2 = 0.f;
            #pragma unroll
            for (int k = 0; k < 8; k++) {
                rna += sh[0][k]; rsa += sh[1][k]; rps += sh[2][k]; rdap2 += sh[3][k];
            }
            g_thresh[i] = has ? (rps - MARGIN_F) : FLT_MAX;
            g_na[i] = rna; g_sa[i] = rsa; g_dap[i] = sqrtf(rdap2);
            if (i == 0) { g_total = 0.0; g_count = 0; }
        }
    }
}

// ---------------- Kernel B: 4-stage pipelined gemm + mask + epilogue + finalize ----------------
__global__ __launch_bounds__(512, 2)
void gemm_kernel(const int* __restrict__ targets_row,
                 float* __restrict__ out, unsigned nblocks) {
    extern __shared__ char dsm[];
    __shared__ float red_s[16];
    __shared__ int   red_c[16];

    uint32_t sb = smem_u32(dsm);
    int tid = threadIdx.x;
    int wid = tid >> 5, lid = tid & 31;
    int j0 = blockIdx.x * BN;

    // warp tiling: 8 (i) x 2 (j); warp tile 32x32
    int i0w = (wid >> 1) * 32, j0w = (wid & 1) * 32;

    float acc[2][4][4];
    #pragma unroll
    for (int a = 0; a < 2; a++)
        #pragma unroll
        for (int b = 0; b < 4; b++)
            #pragma unroll
            for (int c = 0; c < 4; c++) acc[a][b][c] = 0.f;

    uint32_t a_lane = (uint32_t)((lid & 15) * STRB + (lid >> 4) * 16);
    uint32_t b_lane = (uint32_t)(((lid & 7) + ((lid >> 4) & 1) * 8) * STRB + ((lid >> 3) & 1) * 16);

    int*      s_nneg = (int*)(dsm + NNEG_OFF);
    int*      s_trow = (int*)(dsm + TROW_OFF);
    unsigned* s_nn   = (unsigned*)(dsm + NN_OFF);

    // loader mapping
    // A: 1024 granules/chunk -> 2 per thread: g = tid*2+p; row=g>>2, cg=g&3
    // B: 256 granules/chunk  -> threads 0..255: row=tid>>2, cg=tid&3
    int ar0 = (tid * 2) >> 2,     ac0 = (tid * 2) & 3;
    int ar1 = (tid * 2 + 1) >> 2, ac1 = (tid * 2 + 1) & 3;
    const char* Asrc0 = (const char*)(g_Abf + ar0 * DIM + ac0 * 8);
    const char* Asrc1 = (const char*)(g_Abf + ar1 * DIM + ac1 * 8);
    uint32_t Adst0 = (uint32_t)(ar0 * STRB + ac0 * 16);
    uint32_t Adst1 = (uint32_t)(ar1 * STRB + ac1 * 16);
    int brow = tid >> 2, bcg = tid & 3;
    const char* Bsrc = (const char*)(g_Bbf + (size_t)(j0 + brow) * DIM + bcg * 8);
    uint32_t Bdst = (uint32_t)(brow * STRB + bcg * 16);
    bool bload = (tid < 256);

    // ---- prologue ----
    {
        // stage nneg into stage-3 overlay + trow
        #pragma unroll
        for (int p = 0; p < 5; p++) s_nneg[tid + p * 512] = g_nneg[tid + p * 512];
        if (tid < BN) s_trow[tid] = targets_row[j0 + tid];

        // issue chunks 0..2 into stages 0..2
        #pragma unroll
        for (int c = 0; c < NSTAGE - 1; c++) {
            size_t kc = (size_t)c * BKC * 2;
            CP_ASYNC16(sb + A_OFF(c) + Adst0, Asrc0 + kc);
            CP_ASYNC16(sb + A_OFF(c) + Adst1, Asrc1 + kc);
            if (bload) CP_ASYNC16(sb + B_OFF(c) + Bdst, Bsrc + kc);
            CP_COMMIT();
        }
        __syncthreads();   // nneg/trow staging visible

        // mask compute: warp handles 8 groups x 4 rows
        {
            int myneg[KNEG];
            #pragma unroll 1
            for (int g = 0; g < 8; g++) {
                int i = g * 32 + lid;
                #pragma unroll
                for (int k = 0; k < KNEG; k++) myneg[k] = s_nneg[i * KNEG + k];
                #pragma unroll
                for (int r = 0; r < 4; r++) {
                    int rrow = wid * 4 + r;
                    int t = s_trow[rrow];
                    bool m = false;
                    #pragma unroll
                    for (int k = 0; k < KNEG; k++) m = m || (myneg[k] == t);
                    unsigned word = __ballot_sync(0xffffffffu, m);
                    if (lid == 0) s_nn[rrow * 8 + g] = word;
                }
            }
        }
    }

    // ---- mainloop: at iter kt, wait for chunk kt (<=2 groups incomplete), sync,
    //      issue chunk kt+3 into stage (kt+3)&3, compute stage kt&3 ----
    #pragma unroll 1
    for (int kt = 0; kt < NCHUNK; kt++) {
        CP_WAIT(2);
        __syncthreads();

        if (kt + 3 < NCHUNK) {
            int st = (kt + 3) & 3;
            size_t kc = (size_t)(kt + 3) * BKC * 2;
            CP_ASYNC16(sb + A_OFF(st) + Adst0, Asrc0 + kc);
            CP_ASYNC16(sb + A_OFF(st) + Adst1, Asrc1 + kc);
            if (bload) CP_ASYNC16(sb + B_OFF(st) + Bdst, Bsrc + kc);
            CP_COMMIT();
        }

        uint32_t Ab = sb + A_OFF(kt & 3);
        uint32_t Bb = sb + B_OFF(kt & 3);
        #pragma unroll
        for (int ks = 0; ks < BKC; ks += 16) {
            uint32_t afr[2][4], bfr[2][4];
            #pragma unroll
            for (int mt = 0; mt < 2; mt++)
                ldsm_x4(afr[mt], Ab + (uint32_t)((i0w + mt * 16) * STRB + ks * 2) + a_lane);
            #pragma unroll
            for (int np = 0; np < 2; np++)
                ldsm_x4(bfr[np], Bb + (uint32_t)((j0w + np * 16) * STRB + ks * 2) + b_lane);
            #pragma unroll
            for (int mt = 0; mt < 2; mt++) {
                #pragma unroll
                for (int np = 0; np < 2; np++) {
                    mma16816(acc[mt][np * 2 + 0], afr[mt], bfr[np][0], bfr[np][1]);
                    mma16816(acc[mt][np * 2 + 1], afr[mt], bfr[np][2], bfr[np][3]);
                }
            }
        }
    }
    __syncthreads();   // all compute done before stage-0 overlay

    // ---- epilogue tables (overlay stage 0) ----
    float* s_th  = (float*)(dsm + T_TH);
    float* s_na  = (float*)(dsm + T_NA);
    float* s_sa  = (float*)(dsm + T_SA);
    float* s_dap = (float*)(dsm + T_DAP);
    float* s_nb  = (float*)(dsm + T_NB);
    float* s_sb  = (float*)(dsm + T_SB);

    if (tid < 256) {
        s_th[tid]  = g_thresh[tid];
        s_na[tid]  = g_na[tid];
        s_sa[tid]  = g_sa[tid];
        s_dap[tid] = g_dap[tid];
    }
    if (tid < BN) {
        s_nb[tid] = g_nb[j0 + tid];
        s_sb[tid] = g_sb[j0 + tid];
    }
    __syncthreads();

    const float cterm = (float)DIM * EPS_F * EPS_F;
    float sumtl = 0.f;
    int cnt = 0;
    #pragma unroll
    for (int mt = 0; mt < 2; mt++) {
        int i1 = i0w + mt * 16 + (lid >> 2);
        int i2 = i1 + 8;
        float th1 = s_th[i1], na1 = s_na[i1], sa1 = s_sa[i1], dp1 = s_dap[i1];
        float th2 = s_th[i2], na2 = s_na[i2], sa2 = s_sa[i2], dp2 = s_dap[i2];
        int g1 = i1 >> 5, g2 = i2 >> 5;
        unsigned bit1 = 1u << (i1 & 31), bit2 = 1u << (i2 & 31);
        #pragma unroll
        for (int nt = 0; nt < 4; nt++) {
            int jl = j0w + nt * 8 + (lid & 3) * 2;
            #pragma unroll
            for (int c = 0; c < 4; c++) {
                int jj = jl + (c & 1);
                float s = acc[mt][nt][c];
                float th  = (c < 2) ? th1 : th2;
                unsigned bit = (c < 2) ? bit1 : bit2;
                int g = (c < 2) ? g1 : g2;
                if (s > th && !(s_nn[jj * 8 + g] & bit)) {
                    float na = (c < 2) ? na1 : na2;
                    float sa = (c < 2) ? sa1 : sa2;
                    float dp = (c < 2) ? dp1 : dp2;
                    cnt++;
                    float dan2 = na + s_nb[jj] - 2.0f * s
                               + 2.0f * EPS_F * (sa - s_sb[jj]) + cterm;
                    float dan = sqrtf(fmaxf(dan2, 0.0f));
                    float tl = dp - dan + TMARGIN_F;
                    if (tl > 0.0f) sumtl += tl;
                }
            }
        }
    }
    sumtl = warpReduceSum(sumtl);
    cnt   = warpReduceSumI(cnt);
    if (lid == 0) { red_s[wid] = sumtl; red_c[wid] = cnt; }
    __syncthreads();
    if (tid == 0) {
        float ts = 0.f; int tc = 0;
        #pragma unroll
        for (int w = 0; w < 16; w++) { ts += red_s[w]; tc += red_c[w]; }
        if (tc > 0) { atomicAdd(&g_total, (double)ts); atomicAdd(&g_count, tc); }
        __threadfence();
        unsigned d = atomicAdd(&g_done, 1u);
        if (d == nblocks - 1) {
            g_done = 0;
            __threadfence();
            int c = g_count;
            out[0] = (c > 0) ? (float)(g_total / (double)c) : 0.0f;
        }
    }
}

extern "C" void kernel_launch(void* const* d_in, const int* in_sizes, int n_in,
                              void* d_out, int out_size) {
    const float* inputs_col  = (const float*)d_in[0];
    const float* inputs_row  = (const float*)d_in[1];
    const int*   targets_col = (const int*)d_in[2];
    const int*   targets_row = (const int*)d_in[3];
    const int*   qidxs       = (const int*)d_in[4];
    // d_in[5] = pidxs: dead in the reference loss
    const int*   nnegs       = (const int*)d_in[6];

    cudaFuncSetAttribute(gemm_kernel, cudaFuncAttributeMaxDynamicSharedMemorySize, SMEM_DYN);

    prep_kernel<<<CONV_BLOCKS + BSZ, 256>>>(inputs_col, inputs_row, targets_col,
                                            qidxs, nnegs);
    gemm_kernel<<<MROW / BN, 512, SMEM_DYN>>>(targets_row, (float*)d_out, MROW / BN);
}

// round 11
// speedup vs baseline: 1.1411x; 1.1411x over previous
#include <cuda_runtime.h>
#include <cuda_bf16.h>
#include <math.h>
#include <float.h>
#include <stdint.h>

#define BSZ   256
#define MROW  32768
#define DIM   512
#define KNEG  10
#define MARGIN_F 0.1f
#define EPS_F 1e-6f
#define TMARGIN_F 0.31622776601683794f

#define BM 128              // i rows per CTA
#define BN 64               // j rows per CTA
#define BKC 64              // K per chunk (bf16)
#define NCHUNK (DIM / BKC)  // 8
#define PADK 72             // padded k-stride (144 B), ldsm conflict-free
#define STRB (PADK * 2)

// dynamic smem (bytes)
#define A_T0   0
#define A_T1   18432            // 128*144
#define B_T0   36864
#define B_T1   46080            // + 64*144
#define NN_OFF 55296            // 64*4 u32 = 1024
#define NNEG_OFF 56320          // 128*10 int = 5120
#define TROW_OFF 61440          // 64 int
#define SMEM_DYN 61696
// epilogue tables overlay stage A_T0
#define T_TH  0
#define T_NA  512
#define T_SA  1024
#define T_DAP 1536
#define T_NB  2048
#define T_SB  2304

#define CONV_BLOCKS (MROW / 8)  // 4096

// ---------------- scratch globals ----------------
__device__ float         g_thresh[BSZ];
__device__ float         g_na[BSZ];
__device__ float         g_sa[BSZ];
__device__ float         g_dap[BSZ];
__device__ int           g_nneg[BSZ * KNEG];
__device__ float         g_nb[MROW];
__device__ float         g_sb[MROW];
__device__ __align__(256) __nv_bfloat16 g_Abf[BSZ * DIM];
__device__ __align__(256) __nv_bfloat16 g_Bbf[(size_t)MROW * DIM];
__device__ double        g_total;
__device__ int           g_count;
__device__ unsigned      g_done = 0;

// ---------------- helpers ----------------
__device__ __forceinline__ uint32_t smem_u32(const void* p) {
    uint32_t a;
    asm("{ .reg .u64 t; cvta.to.shared.u64 t, %1; cvt.u32.u64 %0, t; }" : "=r"(a) : "l"(p));
    return a;
}
__device__ __forceinline__ void ldsm_x4(uint32_t* r, uint32_t addr) {
    asm volatile("ldmatrix.sync.aligned.m8n8.x4.shared.b16 {%0,%1,%2,%3}, [%4];"
                 : "=r"(r[0]), "=r"(r[1]), "=r"(r[2]), "=r"(r[3]) : "r"(addr));
}
__device__ __forceinline__ void mma16816(float* d, const uint32_t* a, uint32_t b0, uint32_t b1) {
    asm volatile(
        "mma.sync.aligned.m16n8k16.row.col.f32.bf16.bf16.f32 "
        "{%0,%1,%2,%3}, {%4,%5,%6,%7}, {%8,%9}, {%0,%1,%2,%3};"
        : "+f"(d[0]), "+f"(d[1]), "+f"(d[2]), "+f"(d[3])
        : "r"(a[0]), "r"(a[1]), "r"(a[2]), "r"(a[3]), "r"(b0), "r"(b1));
}
#define CP_ASYNC16(dst, src) \
    asm volatile("cp.async.cg.shared.global [%0], [%1], 16;" :: "r"(dst), "l"(src))
#define CP_COMMIT()  asm volatile("cp.async.commit_group;" ::: "memory")
#define CP_WAIT0()   asm volatile("cp.async.wait_group 0;" ::: "memory")

__inline__ __device__ float warpReduceSum(float v) {
    #pragma unroll
    for (int o = 16; o > 0; o >>= 1) v += __shfl_down_sync(0xffffffffu, v, o);
    return v;
}
__inline__ __device__ int warpReduceSumI(int v) {
    #pragma unroll
    for (int o = 16; o > 0; o >>= 1) v += __shfl_down_sync(0xffffffffu, v, o);
    return v;
}
__device__ __forceinline__ uint32_t packbf(float x, float y) {
    __nv_bfloat162 t = __float22bfloat162_rn(make_float2(x, y));
    return *(uint32_t*)&t;
}

// ---------------- Kernel A: prep (B convert + stats | per-query setup) ----------------
__global__ __launch_bounds__(256)
void prep_kernel(const float* __restrict__ col,
                 const float* __restrict__ row,
                 const int* __restrict__ targets_col,
                 const int* __restrict__ qidxs,
                 const int* __restrict__ nnegs) {
    int bid = blockIdx.x;
    int tid = threadIdx.x;
    int w = tid >> 5, lid = tid & 31;

    if (bid < CONV_BLOCKS) {
        int j = bid * 8 + w;
        const float4* src = (const float4*)(row + (size_t)j * DIM);
        uint2* dst = (uint2*)(g_Bbf + (size_t)j * DIM);
        float nb = 0.f, sb = 0.f;
        #pragma unroll
        for (int t = 0; t < 4; t++) {
            float4 v = src[lid + t * 32];
            nb += v.x*v.x + v.y*v.y + v.z*v.z + v.w*v.w;
            sb += v.x + v.y + v.z + v.w;
            uint2 pk;
            pk.x = packbf(v.x, v.y);
            pk.y = packbf(v.z, v.w);
            dst[lid + t * 32] = pk;
        }
        nb = warpReduceSum(nb);
        sb = warpReduceSum(sb);
        if (lid == 0) { g_nb[j] = nb; g_sb[j] = sb; }
        return;
    }

    int i = bid - CONV_BLOCKS;
    const float* q = col + (size_t)i * DIM;
    const float* p = row + (size_t)(BSZ + i) * DIM;

    float na = 0.f, sa = 0.f, ps = 0.f, dap2 = 0.f;
    #pragma unroll
    for (int t = 0; t < 2; t++) {
        int k = tid + t * 256;
        float qv = q[k], pv = p[k];
        na += qv * qv;
        sa += qv;
        ps += qv * pv;
        float dlt = qv - pv + EPS_F;
        dap2 += dlt * dlt;
        g_Abf[i * DIM + k] = __float2bfloat16_rn(qv);
    }
    __shared__ float sh[4][8];
    na = warpReduceSum(na); sa = warpReduceSum(sa);
    ps = warpReduceSum(ps); dap2 = warpReduceSum(dap2);
    if (lid == 0) { sh[0][w] = na; sh[1][w] = sa; sh[2][w] = ps; sh[3][w] = dap2; }
    __syncthreads();

    if (w == 0) {
        int tc = targets_col[i];
        int qloc = 0, has = 0;
        #pragma unroll
        for (int g = 0; g < 8; g++) {
            int qv = qidxs[g * 32 + lid];
            unsigned word = __ballot_sync(0xffffffffu, qv == tc);
            if (!has && word) { qloc = g * 32 + __ffs(word) - 1; has = 1; }
        }
        if (lid < KNEG) g_nneg[i * KNEG + lid] = nnegs[qloc * KNEG + lid];
        if (lid == 0) {
            float rna = 0.f, rsa = 0.f, rps = 0.f, rdap2 = 0.f;
            #pragma unroll
            for (int k = 0; k < 8; k++) {
                rna += sh[0][k]; rsa += sh[1][k]; rps += sh[2][k]; rdap2 += sh[3][k];
            }
            g_thresh[i] = has ? (rps - MARGIN_F) : FLT_MAX;
            g_na[i] = rna; g_sa[i] = rsa; g_dap[i] = sqrtf(rdap2);
            if (i == 0) { g_total = 0.0; g_count = 0; }
        }
    }
}

// ---------------- Kernel B: gemm (BM=128, 3 CTAs/SM, frag-pipelined) ----------------
__global__ __launch_bounds__(256, 3)
void gemm_kernel(const int* __restrict__ targets_row,
                 float* __restrict__ out, unsigned nblocks) {
    extern __shared__ char dsm[];
    __shared__ float red_s[8];
    __shared__ int   red_c[8];

    uint32_t sb = smem_u32(dsm);
    int tid = threadIdx.x;
    int wid = tid >> 5, lid = tid & 31;
    int bid = blockIdx.x;
    int j0    = (bid >> 1) * BN;      // paired CTAs share B (L2 reuse)
    int ihalf = bid & 1;
    int ibase = ihalf * BM;

    // warp tiling: 4 (i) x 2 (j); warp tile 32x32
    int i0w = (wid >> 1) * 32, j0w = (wid & 1) * 32;

    float acc[2][4][4];
    #pragma unroll
    for (int a = 0; a < 2; a++)
        #pragma unroll
        for (int b = 0; b < 4; b++)
            #pragma unroll
            for (int c = 0; c < 4; c++) acc[a][b][c] = 0.f;

    uint32_t a_lane = (uint32_t)((lid & 15) * STRB + (lid >> 4) * 16);
    uint32_t b_lane = (uint32_t)(((lid & 7) + ((lid >> 4) & 1) * 8) * STRB + ((lid >> 3) & 1) * 16);

    int*      s_nneg = (int*)(dsm + NNEG_OFF);
    int*      s_trow = (int*)(dsm + TROW_OFF);
    unsigned* s_nn   = (unsigned*)(dsm + NN_OFF);

    // loader mapping: granule row = tid>>3 (+32/p), col granule = tid&7
    int grow = tid >> 3, gcol = tid & 7;
    const char* Asrc = (const char*)(g_Abf + (size_t)(ibase + grow) * DIM) + gcol * 16;
    const char* Bsrc = (const char*)(g_Bbf + (size_t)(j0 + grow) * DIM) + gcol * 16;
    uint32_t gdst = (uint32_t)(grow * STRB + gcol * 16);
    const size_t ASTEP = (size_t)32 * DIM * 2;   // 32 rows forward
    const uint32_t SSTEP = 32 * STRB;

    // ---- prologue ----
    {
        #pragma unroll
        for (int p = 0; p < 5; p++) s_nneg[tid + p * 256] = g_nneg[ibase * KNEG + tid + p * 256];
        if (tid < BN) s_trow[tid] = targets_row[j0 + tid];

        // chunk 0 -> stage 0
        #pragma unroll
        for (int p = 0; p < 4; p++)
            CP_ASYNC16(sb + A_T0 + gdst + p * SSTEP, Asrc + p * ASTEP);
        #pragma unroll
        for (int p = 0; p < 2; p++)
            CP_ASYNC16(sb + B_T0 + gdst + p * SSTEP, Bsrc + p * ASTEP);
        CP_COMMIT();
        __syncthreads();   // nneg/trow visible

        // mask: warp handles rows wid*8..+7, 4 local-i groups
        {
            int myneg[KNEG];
            #pragma unroll 1
            for (int g = 0; g < 4; g++) {
                int il = g * 32 + lid;
                #pragma unroll
                for (int k = 0; k < KNEG; k++) myneg[k] = s_nneg[il * KNEG + k];
                #pragma unroll
                for (int r = 0; r < 8; r++) {
                    int rrow = wid * 8 + r;
                    int t = s_trow[rrow];
                    bool m = false;
                    #pragma unroll
                    for (int k = 0; k < KNEG; k++) m = m || (myneg[k] == t);
                    unsigned word = __ballot_sync(0xffffffffu, m);
                    if (lid == 0) s_nn[rrow * 4 + g] = word;
                }
            }
        }
        CP_WAIT0();
        __syncthreads();
    }

    // ---- mainloop: 2-stage, BKC=64, frag double-buffer, warp-staggered ks ----
    int krot = wid & 3;
    #pragma unroll 1
    for (int kt = 0; kt < NCHUNK; kt++) {
        int buf = kt & 1;
        uint32_t Ab = sb + (buf ? A_T1 : A_T0);
        uint32_t Bb;
        if (buf) Bb = sb + B_T1; else Bb = sb + B_T0;

        if (kt < NCHUNK - 1) {
            uint32_t AbN = sb + (buf ? A_T0 : A_T1);
            uint32_t BbN = sb + (buf ? B_T0 : B_T1);
            size_t kc = (size_t)(kt + 1) * BKC * 2;
            #pragma unroll
            for (int p = 0; p < 4; p++)
                CP_ASYNC16(AbN + gdst + p * SSTEP, Asrc + p * ASTEP + kc);
            #pragma unroll
            for (int p = 0; p < 2; p++)
                CP_ASYNC16(BbN + gdst + p * SSTEP, Bsrc + p * ASTEP + kc);
            CP_COMMIT();
        }

        // fragment double-buffered ks loop, staggered start per warp
        uint32_t afr[2][2][4], bfr[2][2][4];
        {
            int ks = krot * 16;
            #pragma unroll
            for (int mt = 0; mt < 2; mt++)
                ldsm_x4(afr[0][mt], Ab + (uint32_t)((i0w + mt * 16) * STRB + ks * 2) + a_lane);
            #pragma unroll
            for (int np = 0; np < 2; np++)
                ldsm_x4(bfr[0][np], Bb + (uint32_t)((j0w + np * 16) * STRB + ks * 2) + b_lane);
        }
        #pragma unroll
        for (int s = 0; s < 4; s++) {
            int cb = s & 1, nb = cb ^ 1;
            if (s < 3) {
                int ksn = ((s + 1 + krot) & 3) * 16;
                #pragma unroll
                for (int mt = 0; mt < 2; mt++)
                    ldsm_x4(afr[nb][mt], Ab + (uint32_t)((i0w + mt * 16) * STRB + ksn * 2) + a_lane);
                #pragma unroll
                for (int np = 0; np < 2; np++)
                    ldsm_x4(bfr[nb][np], Bb + (uint32_t)((j0w + np * 16) * STRB + ksn * 2) + b_lane);
            }
            #pragma unroll
            for (int mt = 0; mt < 2; mt++) {
                #pragma unroll
                for (int np = 0; np < 2; np++) {
                    mma16816(acc[mt][np * 2 + 0], afr[cb][mt], bfr[cb][np][0], bfr[cb][np][1]);
                    mma16816(acc[mt][np * 2 + 1], afr[cb][mt], bfr[cb][np][2], bfr[cb][np][3]);
                }
            }
        }

        if (kt < NCHUNK - 1) CP_WAIT0();
        __syncthreads();
    }

    // ---- epilogue tables (overlay stage A_T0) ----
    float* s_th  = (float*)(dsm + T_TH);
    float* s_na  = (float*)(dsm + T_NA);
    float* s_sa  = (float*)(dsm + T_SA);
    float* s_dap = (float*)(dsm + T_DAP);
    float* s_nb  = (float*)(dsm + T_NB);
    float* s_sb  = (float*)(dsm + T_SB);

    if (tid < BM) {
        int gi = ibase + tid;
        s_th[tid]  = g_thresh[gi];
        s_na[tid]  = g_na[gi];
        s_sa[tid]  = g_sa[gi];
        s_dap[tid] = g_dap[gi];
    }
    if (tid < BN) {
        s_nb[tid] = g_nb[j0 + tid];
        s_sb[tid] = g_sb[j0 + tid];
    }
    __syncthreads();

    const float cterm = (float)DIM * EPS_F * EPS_F;
    float sumtl = 0.f;
    int cnt = 0;
    #pragma unroll
    for (int mt = 0; mt < 2; mt++) {
        int i1 = i0w + mt * 16 + (lid >> 2);     // local i in [0,128)
        int i2 = i1 + 8;
        float th1 = s_th[i1], na1 = s_na[i1], sa1 = s_sa[i1], dp1 = s_dap[i1];
        float th2 = s_th[i2], na2 = s_na[i2], sa2 = s_sa[i2], dp2 = s_dap[i2];
        int g1 = i1 >> 5, g2 = i2 >> 5;
        unsigned bit1 = 1u << (i1 & 31), bit2 = 1u << (i2 & 31);
        #pragma unroll
        for (int nt = 0; nt < 4; nt++) {
            int jl = j0w + nt * 8 + (lid & 3) * 2;
            #pragma unroll
            for (int c = 0; c < 4; c++) {
                int jj = jl + (c & 1);
                float s = acc[mt][nt][c];
                float th  = (c < 2) ? th1 : th2;
                unsigned bit = (c < 2) ? bit1 : bit2;
                int g = (c < 2) ? g1 : g2;
                if (s > th && !(s_nn[jj * 4 + g] & bit)) {
                    float na = (c < 2) ? na1 : na2;
                    float sa = (c < 2) ? sa1 : sa2;
                    float dp = (c < 2) ? dp1 : dp2;
                    cnt++;
                    float dan2 = na + s_nb[jj] - 2.0f * s
                               + 2.0f * EPS_F * (sa - s_sb[jj]) + cterm;
                    float dan = sqrtf(fmaxf(dan2, 0.0f));
                    float tl = dp - dan + TMARGIN_F;
                    if (tl > 0.0f) sumtl += tl;
                }
            }
        }
    }
    sumtl = warpReduceSum(sumtl);
    cnt   = warpReduceSumI(cnt);
    if (lid == 0) { red_s[wid] = sumtl; red_c[wid] = cnt; }
    __syncthreads();
    if (tid == 0) {
        float ts = 0.f; int tc = 0;
        #pragma unroll
        for (int w = 0; w < 8; w++) { ts += red_s[w]; tc += red_c[w]; }
        if (tc > 0) { atomicAdd(&g_total, (double)ts); atomicAdd(&g_count, tc); }
        __threadfence();
        unsigned d = atomicAdd(&g_done, 1u);
        if (d == nblocks - 1) {
            g_done = 0;
            __threadfence();
            int c = g_count;
            out[0] = (c > 0) ? (float)(g_total / (double)c) : 0.0f;
        }
    }
}

extern "C" void kernel_launch(void* const* d_in, const int* in_sizes, int n_in,
                              void* d_out, int out_size) {
    const float* inputs_col  = (const float*)d_in[0];
    const float* inputs_row  = (const float*)d_in[1];
    const int*   targets_col = (const int*)d_in[2];
    const int*   targets_row = (const int*)d_in[3];
    const int*   qidxs       = (const int*)d_in[4];
    // d_in[5] = pidxs: dead in the reference loss
    const int*   nnegs       = (const int*)d_in[6];

    cudaFuncSetAttribute(gemm_kernel, cudaFuncAttributeMaxDynamicSharedMemorySize, SMEM_DYN);

    prep_kernel<<<CONV_BLOCKS + BSZ, 256>>>(inputs_col, inputs_row, targets_col,
                                            qidxs, nnegs);
    unsigned nblocks = (MROW / BN) * 2;   // 1024
    gemm_kernel<<<nblocks, 256, SMEM_DYN>>>(targets_row, (float*)d_out, nblocks);
}